// round 8
// baseline (speedup 1.0000x reference)
#include <cuda_runtime.h>
#include <cstdint>

#define NDIM 4096
#define STRIDE 640
#define NBLOCKS 128
#define NTHREADS 1024
#define ROWS_PER_CTA (NTHREADS / 32)

// Static scratch (no allocations allowed). SoA layout:
//   g_cols: u16 column index per nnz slot (5.2 MB)
//   g_vals: float2 (C, S) per nnz slot   (21 MB)
__device__ __align__(16) unsigned short g_cols[NDIM * STRIDE];
__device__ __align__(16) float2         g_vals[NDIM * STRIDE];
__device__ int g_cnt[NDIM];            // raw nnz
__device__ int g_nnz[NDIM];            // padded nnz (512 or 640)
__device__ int g_bar_count;
__device__ int g_bar_release;

// Cheap tanh for |x| <~ 0.5 (Taylor through x^9), fallback tanhf. FMA pipe only.
__device__ __forceinline__ float tanh_fast(float x) {
    if (fabsf(x) > 0.5f) return tanhf(x);
    float x2 = x * x;
    float p = 0.02186948853f;
    p = fmaf(p, x2, -0.05396825397f);
    p = fmaf(p, x2,  0.13333333333f);
    p = fmaf(p, x2, -0.33333333333f);
    return fmaf(p * x2, x, x);
}

// sin/cos on the FMA pipe (Taylor, |x|<=1: err < 3e-6), MUFU fallback outside.
__device__ __forceinline__ void sincos_poly(float x, float* s, float* c) {
    if (fabsf(x) > 1.0f) { __sincosf(x, s, c); return; }
    float x2 = x * x;
    float ps = -1.9841270114e-4f;
    ps = fmaf(ps, x2, 8.3333337680e-3f);
    ps = fmaf(ps, x2, -1.6666667163e-1f);
    *s = fmaf(ps * x2, x, x);
    float pc = 2.4801587642e-5f;
    pc = fmaf(pc, x2, -1.3888888899e-3f);
    pc = fmaf(pc, x2, 4.1666667908e-2f);
    pc = fmaf(pc, x2, -0.5f);
    *c = fmaf(pc, x2, 1.0f);
}

// Phase A: mask scan + column compaction. One warp per row; 4 mask loads
// batched ahead of their ballots to break the load->ballot serial chain.
__global__ void cols_kernel(const float* __restrict__ Amask) {
    if (blockIdx.x == 0 && threadIdx.x == 0) {      // fused barrier init
        g_bar_count = 0;
        g_bar_release = 0;
    }
    int warp = threadIdx.x >> 5;
    int lane = threadIdx.x & 31;
    int row  = blockIdx.x * 8 + warp;
    if (row >= NDIM) return;
    size_t base  = (size_t)row * NDIM;
    int    obase = row * STRIDE;
    int    cnt   = 0;
    for (int j0 = 0; j0 < NDIM; j0 += 128) {
        float m0 = Amask[base + j0 + lane];
        float m1 = Amask[base + j0 + 32 + lane];
        float m2 = Amask[base + j0 + 64 + lane];
        float m3 = Amask[base + j0 + 96 + lane];
        #define COMPACT(mv, off) {                                        \
            unsigned b = __ballot_sync(0xffffffffu, (mv) != 0.0f);        \
            if ((mv) != 0.0f) {                                           \
                int p = cnt + __popc(b & ((1u << lane) - 1u));            \
                if (p < STRIDE)                                           \
                    g_cols[obase + p] = (unsigned short)(j0 + (off) + lane); \
            }                                                             \
            cnt += __popc(b);                                             \
        }
        COMPACT(m0, 0); COMPACT(m1, 32); COMPACT(m2, 64); COMPACT(m3, 96);
        #undef COMPACT
    }
    if (cnt > STRIDE) cnt = STRIDE;
    // Pad to 512 minimum (fixed 4-chunk main loop), or 640 for long rows.
    int nnz_pad = (cnt <= 512) ? 512 : STRIDE;
    for (int k = cnt + lane; k < nnz_pad; k += 32) {
        g_cols[obase + k] = 0;
        g_vals[obase + k] = make_float2(0.0f, 0.0f);   // zero coeff
    }
    if (lane == 0) { g_cnt[row] = cnt; g_nnz[row] = nnz_pad; }
}

// Phase B: one thread per nnz slot; fully independent gather + value compute.
// A_mask is binary by construction (max(bernoulli, eye)) so nonzero => 1.0:
// skip its gather entirely.
__global__ void vals_kernel(const float* __restrict__ rawS,
                            const float* __restrict__ rawPhase,
                            const float* __restrict__ rawR,
                            const float* __restrict__ Ggate) {
    int k = blockIdx.x * blockDim.x + threadIdx.x;
    if (k >= NDIM * STRIDE) return;
    int row = k / STRIDE;
    int j   = k - row * STRIDE;
    if (j >= g_cnt[row]) return;
    unsigned col = g_cols[k];
    size_t idx = (size_t)row * NDIM + col;
    float ts = tanh_fast(rawS[idx]);
    float rr = __fdividef(1.0f, 1.0f + __expf(-rawR[idx]));   // 2 MUFU
    float a  = Ggate[idx] * ts * rr;
    float sp, cp;
    sincos_poly(rawPhase[idx], &sp, &cp);                     // 0 MUFU
    g_vals[k] = make_float2(a * cp, a * sp);
}

// Persistent stepping kernel: 128 CTAs x 1024 threads = 4096 warps = 1 row/warp.
// x_{t+1}[r] = tanh( e^{i*omega*t} * (M @ x_t) )  componentwise (complex).
__global__ void __launch_bounds__(NTHREADS, 1)
step_kernel(const float2* __restrict__ x0, float2* __restrict__ out,
            const float* __restrict__ omega_p, int steps) {
    __shared__ float2 xs[NDIM];                // 32 KB fp32 staging of x_t
    int tid  = threadIdx.x;
    int warp = tid >> 5;
    int lane = tid & 31;
    int row  = blockIdx.x * ROWS_PER_CTA + warp;

    float omega = *omega_p;
    int   nnz_pad = g_nnz[row];                // 512 or 640
    const unsigned short* cp = g_cols + row * STRIDE;
    const float2*         vp = g_vals + row * STRIDE;

    for (int t = 0; t < steps; ++t) {
        // Load x_t into shared; on step 0 also emit this CTA's slice of out[0].
        const float2* src = (t == 0) ? x0 : out + (size_t)t * NDIM;
        for (int i = tid; i < NDIM; i += NTHREADS) {
            float2 xv = src[i];
            xs[i] = xv;
            if (t == 0 && (i >> 5) == (int)blockIdx.x) out[i] = xv;
        }
        __syncthreads();

        // Sparse complex matvec: fixed 4 chunks of 128 entries, fully
        // unrolled; each lane takes 4 consecutive entries per chunk
        // (1 x ushort4 + 2 x float4 batched loads, all fp32 math).
        float u = 0.0f, v = 0.0f;
        #define DO_CHUNK(CH) {                                               \
            int k = (CH) * 128 + lane * 4;                                   \
            ushort4 c4  = *reinterpret_cast<const ushort4*>(cp + k);         \
            float4  v01 = *reinterpret_cast<const float4*>(vp + k);          \
            float4  v23 = *reinterpret_cast<const float4*>(vp + k + 2);      \
            float2 xa = xs[c4.x], xb = xs[c4.y], xc = xs[c4.z], xd = xs[c4.w]; \
            u = fmaf(v01.x, xa.x, u); u = fmaf(-v01.y, xa.y, u);             \
            v = fmaf(v01.y, xa.x, v); v = fmaf(v01.x, xa.y, v);              \
            u = fmaf(v01.z, xb.x, u); u = fmaf(-v01.w, xb.y, u);             \
            v = fmaf(v01.w, xb.x, v); v = fmaf(v01.z, xb.y, v);              \
            u = fmaf(v23.x, xc.x, u); u = fmaf(-v23.y, xc.y, u);             \
            v = fmaf(v23.y, xc.x, v); v = fmaf(v23.x, xc.y, v);              \
            u = fmaf(v23.z, xd.x, u); u = fmaf(-v23.w, xd.y, u);             \
            v = fmaf(v23.w, xd.x, v); v = fmaf(v23.z, xd.y, v);              \
        }
        DO_CHUNK(0); DO_CHUNK(1); DO_CHUNK(2); DO_CHUNK(3);
        if (nnz_pad > 512) DO_CHUNK(4);        // rare long-row tail
        #undef DO_CHUNK

        #pragma unroll
        for (int off = 16; off; off >>= 1) {
            u += __shfl_down_sync(0xffffffffu, u, off);
            v += __shfl_down_sync(0xffffffffu, v, off);
        }
        if (lane == 0) {
            float st, ct;
            sincosf(omega * (float)t, &st, &ct);
            float outr = ct * u - st * v;
            float outi = ct * v + st * u;
            out[(size_t)(t + 1) * NDIM + row] = make_float2(tanhf(outr), tanhf(outi));
        }

        // Grid-wide barrier (monotonic target, no per-step reset).
        if (t + 1 < steps) {
            __syncthreads();
            if (tid == 0) {
                __threadfence();
                int prev = atomicAdd(&g_bar_count, 1);
                if (prev == (t + 1) * NBLOCKS - 1) {
                    atomicExch(&g_bar_release, t + 1);
                } else {
                    while (*((volatile int*)&g_bar_release) < t + 1) { __nanosleep(32); }
                }
            }
            __syncthreads();
        }
    }
}

extern "C" void kernel_launch(void* const* d_in, const int* in_sizes, int n_in,
                              void* d_out, int out_size) {
    const float2* x        = (const float2*)d_in[0];
    const float*  rawS     = (const float*)d_in[1];
    const float*  rawPhase = (const float*)d_in[2];
    const float*  rawR     = (const float*)d_in[3];
    const float*  Ggate    = (const float*)d_in[5];
    const float*  omega    = (const float*)d_in[6];
    (void)in_sizes; (void)n_in;

    // out is (steps+1, N, 2) float32.
    int steps = out_size / (2 * NDIM) - 1;

    cols_kernel<<<NDIM / 8, 256>>>((const float*)d_in[4]);
    vals_kernel<<<(NDIM * STRIDE + 255) / 256, 256>>>(rawS, rawPhase, rawR, Ggate);
    step_kernel<<<NBLOCKS, NTHREADS>>>(x, (float2*)d_out, omega, steps);
}